// round 1
// baseline (speedup 1.0000x reference)
#include <cuda_runtime.h>
#include <cstddef>

// Problem constants (fixed shapes)
#define B_   16
#define N_   4096
#define M_   1024
#define C1_  256
#define C2_  256
#define CO_  256

// GEMM tiling
#define BM 128
#define BN 128
#define BK 16

// ---------------- scratch (device globals; allocation-free rule) -------------
__device__ float g_interp[(size_t)B_ * C2_ * N_];  // interpolated known feats
__device__ float g_h1[(size_t)B_ * CO_ * N_];      // layer1 pre-BN
__device__ float g_h2[(size_t)B_ * CO_ * N_];      // layer2 pre-BN
__device__ int   g_idx[(size_t)B_ * 3 * N_];       // [b][t][n]
__device__ float g_w[(size_t)B_ * 3 * N_];         // [b][t][n]
__device__ float g_sum1[CO_], g_sq1[CO_], g_scale1[CO_], g_shift1[CO_];
__device__ float g_sum2[CO_], g_sq2[CO_], g_scale2[CO_], g_shift2[CO_];

// ---------------- zero stats -------------------------------------------------
__global__ void zero_stats_kernel() {
    int t = threadIdx.x;
    g_sum1[t] = 0.f; g_sq1[t] = 0.f;
    g_sum2[t] = 0.f; g_sq2[t] = 0.f;
}

// ---------------- three_nn: top-3 neighbors + weights ------------------------
__global__ void __launch_bounds__(256) knn_kernel(
    const float* __restrict__ unknown,  // (B, N, 3)
    const float* __restrict__ known)    // (B, M, 3)
{
    __shared__ float4 sk[M_];
    int b = blockIdx.y;
    const float* kb = known + (size_t)b * M_ * 3;
    for (int j = threadIdx.x; j < M_; j += blockDim.x) {
        sk[j] = make_float4(kb[j * 3 + 0], kb[j * 3 + 1], kb[j * 3 + 2], 0.f);
    }
    __syncthreads();

    int i = blockIdx.x * blockDim.x + threadIdx.x;
    const float* up = unknown + ((size_t)b * N_ + i) * 3;
    float px = up[0], py = up[1], pz = up[2];

    float bd0 = 1e30f, bd1 = 1e30f, bd2 = 1e30f;
    int   bi0 = 0,     bi1 = 0,     bi2 = 0;

    #pragma unroll 4
    for (int j = 0; j < M_; ++j) {
        float4 k4 = sk[j];
        float dx = px - k4.x, dy = py - k4.y, dz = pz - k4.z;
        float d = dx * dx + dy * dy + dz * dz;
        if (d < bd2) {
            if (d < bd1) {
                bd2 = bd1; bi2 = bi1;
                if (d < bd0) { bd1 = bd0; bi1 = bi0; bd0 = d; bi0 = j; }
                else         { bd1 = d;   bi1 = j; }
            } else {
                bd2 = d; bi2 = j;
            }
        }
    }

    float r0 = 1.f / (bd0 + 1e-8f);
    float r1 = 1.f / (bd1 + 1e-8f);
    float r2 = 1.f / (bd2 + 1e-8f);
    float rs = r0 + r1 + r2;

    size_t base = (size_t)b * 3 * N_ + i;
    g_idx[base + 0 * N_] = bi0;
    g_idx[base + 1 * N_] = bi1;
    g_idx[base + 2 * N_] = bi2;
    g_w[base + 0 * N_] = r0 / rs;
    g_w[base + 1 * N_] = r1 / rs;
    g_w[base + 2 * N_] = r2 / rs;
}

// ---------------- three_interpolate ------------------------------------------
// Each block: one batch b, 8 channels (rows stay L1-resident: 8 x 4KB),
// idx/weights read once per i and reused for all 8 channels.
__global__ void __launch_bounds__(256) interp_kernel(
    const float* __restrict__ kf)   // known_feats (B, C2, M)
{
    int b = blockIdx.y;
    int cg = blockIdx.x;  // 0..31 -> channels cg*8 .. cg*8+7
    const int*   ib = g_idx + (size_t)b * 3 * N_;
    const float* wb = g_w   + (size_t)b * 3 * N_;

    for (int i = threadIdx.x; i < N_; i += blockDim.x) {
        int i0 = ib[i], i1 = ib[i + N_], i2 = ib[i + 2 * N_];
        float w0 = wb[i], w1 = wb[i + N_], w2 = wb[i + 2 * N_];
        #pragma unroll
        for (int cc = 0; cc < 8; ++cc) {
            int c = cg * 8 + cc;
            const float* row = kf + ((size_t)b * C2_ + c) * M_;
            float v = w0 * row[i0] + w1 * row[i1] + w2 * row[i2];
            g_interp[((size_t)b * C2_ + c) * N_ + i] = v;
        }
    }
}

// ---------------- fp32 SIMT GEMM, double-buffered, 8x8 microtiles ------------
// MODE 0: out=g_h1, A=W1(256x512), B rows: k<256 -> g_interp, else unknow_feats.
// MODE 1: out=g_h2, A=W2(256x256), B rows: relu(scale1[k]*g_h1 + shift1[k]).
template <int MODE>
__global__ void __launch_bounds__(256) gemm_kernel(
    const float* __restrict__ W,
    const float* __restrict__ uf)   // unknow_feats for MODE 0; unused MODE 1
{
    constexpr int Kdim = (MODE == 0) ? 512 : 256;
    constexpr int ntiles = Kdim / BK;

    int b = blockIdx.z;
    int nBase = blockIdx.x * BN;
    int mBase = blockIdx.y * BM;
    int tid = threadIdx.x;
    int tx = tid & 15, ty = tid >> 4;

    __shared__ float As[2][BK][BM];
    __shared__ float Bs[2][BK][BN];

    float acc[8][8];
    #pragma unroll
    for (int i = 0; i < 8; ++i)
        #pragma unroll
        for (int j = 0; j < 8; ++j) acc[i][j] = 0.f;

    float4 rA[2], rB[2];

    auto fetch = [&](int kt) {
        #pragma unroll
        for (int t = 0; t < 2; ++t) {
            int v = tid + t * 256;
            // A: 128 rows x 16 cols
            int arow = v >> 2, ac4 = (v & 3) * 4;
            rA[t] = *(const float4*)(W + (size_t)(mBase + arow) * Kdim + kt * BK + ac4);
            // B: 16 rows x 128 cols
            int kk = v >> 5, n4 = (v & 31) * 4;
            int k = kt * BK + kk;
            const float* src;
            if (MODE == 0) {
                src = (k < C2_) ? (g_interp + ((size_t)b * C2_ + k) * N_)
                                : (uf + ((size_t)b * C1_ + (k - C2_)) * N_);
            } else {
                src = g_h1 + ((size_t)b * CO_ + k) * N_;
            }
            float4 q = *(const float4*)(src + nBase + n4);
            if (MODE == 1) {
                float sc = g_scale1[k], sh = g_shift1[k];
                q.x = fmaxf(fmaf(sc, q.x, sh), 0.f);
                q.y = fmaxf(fmaf(sc, q.y, sh), 0.f);
                q.z = fmaxf(fmaf(sc, q.z, sh), 0.f);
                q.w = fmaxf(fmaf(sc, q.w, sh), 0.f);
            }
            rB[t] = q;
        }
    };
    auto store = [&](int buf) {
        #pragma unroll
        for (int t = 0; t < 2; ++t) {
            int v = tid + t * 256;
            int arow = v >> 2, ac4 = (v & 3) * 4;
            As[buf][ac4 + 0][arow] = rA[t].x;
            As[buf][ac4 + 1][arow] = rA[t].y;
            As[buf][ac4 + 2][arow] = rA[t].z;
            As[buf][ac4 + 3][arow] = rA[t].w;
            int kk = v >> 5, n4 = (v & 31) * 4;
            *(float4*)&Bs[buf][kk][n4] = rB[t];
        }
    };

    fetch(0);
    store(0);
    __syncthreads();

    for (int kt = 0; kt < ntiles; ++kt) {
        int cur = kt & 1;
        if (kt + 1 < ntiles) fetch(kt + 1);   // LDGs in flight over compute

        #pragma unroll
        for (int k = 0; k < BK; ++k) {
            float4 a0 = *(const float4*)&As[cur][k][ty * 8];
            float4 a1 = *(const float4*)&As[cur][k][ty * 8 + 4];
            float4 b0 = *(const float4*)&Bs[cur][k][tx * 8];
            float4 b1 = *(const float4*)&Bs[cur][k][tx * 8 + 4];
            float av[8] = {a0.x, a0.y, a0.z, a0.w, a1.x, a1.y, a1.z, a1.w};
            float bv[8] = {b0.x, b0.y, b0.z, b0.w, b1.x, b1.y, b1.z, b1.w};
            #pragma unroll
            for (int i = 0; i < 8; ++i)
                #pragma unroll
                for (int j = 0; j < 8; ++j)
                    acc[i][j] = fmaf(av[i], bv[j], acc[i][j]);
        }

        if (kt + 1 < ntiles) store(cur ^ 1);
        __syncthreads();
    }

    float* out = (MODE == 0) ? g_h1 : g_h2;
    size_t obase = ((size_t)b * CO_ + mBase) * N_ + nBase;
    #pragma unroll
    for (int i = 0; i < 8; ++i) {
        size_t r = obase + (size_t)(ty * 8 + i) * N_ + tx * 8;
        float4 v0 = make_float4(acc[i][0], acc[i][1], acc[i][2], acc[i][3]);
        float4 v1 = make_float4(acc[i][4], acc[i][5], acc[i][6], acc[i][7]);
        *(float4*)(out + r)     = v0;
        *(float4*)(out + r + 4) = v1;
    }
}

// ---------------- per-channel batch stats ------------------------------------
template <int MODE>
__global__ void __launch_bounds__(256) stats_kernel() {
    const float* X = (MODE == 0) ? g_h1 : g_h2;
    int c = blockIdx.x, b = blockIdx.y;
    const float* p = X + ((size_t)b * CO_ + c) * N_;
    float s = 0.f, q = 0.f;
    for (int i = threadIdx.x; i < N_; i += 256) {
        float v = p[i];
        s += v;
        q += v * v;
    }
    // warp reduce
    #pragma unroll
    for (int o = 16; o > 0; o >>= 1) {
        s += __shfl_down_sync(0xffffffffu, s, o);
        q += __shfl_down_sync(0xffffffffu, q, o);
    }
    __shared__ float ss[8], qq[8];
    int lane = threadIdx.x & 31, wid = threadIdx.x >> 5;
    if (lane == 0) { ss[wid] = s; qq[wid] = q; }
    __syncthreads();
    if (threadIdx.x < 8) {
        s = ss[threadIdx.x];
        q = qq[threadIdx.x];
        #pragma unroll
        for (int o = 4; o > 0; o >>= 1) {
            s += __shfl_down_sync(0xffu, s, o);
            q += __shfl_down_sync(0xffu, q, o);
        }
        if (threadIdx.x == 0) {
            if (MODE == 0) { atomicAdd(&g_sum1[c], s); atomicAdd(&g_sq1[c], q); }
            else           { atomicAdd(&g_sum2[c], s); atomicAdd(&g_sq2[c], q); }
        }
    }
}

// ---------------- fold BN into scale/shift -----------------------------------
template <int MODE>
__global__ void finalize_kernel(const float* __restrict__ g,
                                const float* __restrict__ bb) {
    int c = threadIdx.x;
    float inv = 1.f / (float)(B_ * N_);
    float s  = (MODE == 0) ? g_sum1[c] : g_sum2[c];
    float sq = (MODE == 0) ? g_sq1[c]  : g_sq2[c];
    float mean = s * inv;
    float var  = sq * inv - mean * mean;
    float rstd = rsqrtf(var + 1e-5f);
    float sc = g[c] * rstd;
    float sh = bb[c] - mean * sc;
    if (MODE == 0) { g_scale1[c] = sc; g_shift1[c] = sh; }
    else           { g_scale2[c] = sc; g_shift2[c] = sh; }
}

// ---------------- final BN+ReLU elementwise -----------------------------------
__global__ void __launch_bounds__(256) apply_kernel(float* __restrict__ out) {
    size_t idx = (size_t)blockIdx.x * blockDim.x + threadIdx.x;  // float4 index
    int c = (int)((idx * 4 / N_) % CO_);
    float4 v = ((const float4*)g_h2)[idx];
    float sc = g_scale2[c], sh = g_shift2[c];
    v.x = fmaxf(fmaf(sc, v.x, sh), 0.f);
    v.y = fmaxf(fmaf(sc, v.y, sh), 0.f);
    v.z = fmaxf(fmaf(sc, v.z, sh), 0.f);
    v.w = fmaxf(fmaf(sc, v.w, sh), 0.f);
    ((float4*)out)[idx] = v;
}

// ---------------- launch -------------------------------------------------------
extern "C" void kernel_launch(void* const* d_in, const int* in_sizes, int n_in,
                              void* d_out, int out_size) {
    const float* unknown      = (const float*)d_in[0];  // (16,4096,3)
    const float* known        = (const float*)d_in[1];  // (16,1024,3)
    const float* unknow_feats = (const float*)d_in[2];  // (16,256,4096)
    const float* known_feats  = (const float*)d_in[3];  // (16,256,1024)
    const float* W1 = (const float*)d_in[4];            // (256,512)
    const float* g1 = (const float*)d_in[5];
    const float* b1 = (const float*)d_in[6];
    const float* W2 = (const float*)d_in[7];            // (256,256)
    const float* g2 = (const float*)d_in[8];
    const float* b2 = (const float*)d_in[9];
    float* out = (float*)d_out;

    zero_stats_kernel<<<1, 256>>>();
    knn_kernel<<<dim3(N_ / 256, B_), 256>>>(unknown, known);
    interp_kernel<<<dim3(C2_ / 8, B_), 256>>>(known_feats);

    dim3 ggrid(N_ / BN, CO_ / BM, B_);
    gemm_kernel<0><<<ggrid, 256>>>(W1, unknow_feats);
    stats_kernel<0><<<dim3(CO_, B_), 256>>>();
    finalize_kernel<0><<<1, 256>>>(g1, b1);

    gemm_kernel<1><<<ggrid, 256>>>(W2, nullptr);
    stats_kernel<1><<<dim3(CO_, B_), 256>>>();
    finalize_kernel<1><<<1, 256>>>(g2, b2);

    apply_kernel<<<(B_ * CO_ * (N_ / 4)) / 256, 256>>>(out);
}

// round 3
// speedup vs baseline: 2.0915x; 2.0915x over previous
#include <cuda_runtime.h>
#include <cuda_bf16.h>
#include <cstdint>
#include <cstddef>

#define B_   16
#define N_   4096
#define M_   1024
#define C1_  256
#define C2_  256
#define CO_  256

// GEMM tile geometry
#define TM 256          // co per block (all of them)
#define TN 128          // n per block
#define KC 32           // original-K chunk
#define ROWPAD 36       // smem row length in bf16 elems (32 + 4 pad)
// smem byte offsets (dynamic smem)
#define A_STAGE_BYTES 36864   // 2 (hi/lo) * 256 * 36 * 2B
#define A_HL_BYTES    18432
#define B_BASE        73728
#define B_STAGE_BYTES 18432   // 2 (hi/lo) * 128 * 36 * 2B
#define B_HL_BYTES     9216
#define SMEM_TOTAL    110592

// ---------------- scratch (device globals) ------------------------------------
__device__ float g_interp[(size_t)B_ * C2_ * N_];
__device__ float g_h1[(size_t)B_ * CO_ * N_];
__device__ float g_h2[(size_t)B_ * CO_ * N_];
__device__ int   g_idx[(size_t)B_ * 3 * N_];
__device__ float g_w[(size_t)B_ * 3 * N_];
__device__ float g_sum1[CO_], g_sq1[CO_], g_scale1[CO_], g_shift1[CO_];
__device__ float g_sum2[CO_], g_sq2[CO_], g_scale2[CO_], g_shift2[CO_];
// weight smem-images: [chunk][hl][256 co][36 kk] bf16
__device__ __nv_bfloat16 g_w1img[16 * 2 * 256 * ROWPAD];
__device__ __nv_bfloat16 g_w2img[8 * 2 * 256 * ROWPAD];

// ---------------- helpers ------------------------------------------------------
__device__ __forceinline__ uint32_t smem_u32(const void* p) {
    uint32_t a;
    asm("{ .reg .u64 t; cvta.to.shared.u64 t, %1; cvt.u32.u64 %0, t; }" : "=r"(a) : "l"(p));
    return a;
}
#define CP_ASYNC16(dst, src) \
    asm volatile("cp.async.cg.shared.global [%0], [%1], 16;" :: "r"(dst), "l"(src))
#define CP_COMMIT() asm volatile("cp.async.commit_group;")
#define CP_WAIT0()  asm volatile("cp.async.wait_group 0;")

__device__ __forceinline__ void mma16816(float c[4], const uint32_t a[4], const uint32_t b[2]) {
    asm volatile(
        "mma.sync.aligned.m16n8k16.row.col.f32.bf16.bf16.f32 "
        "{%0,%1,%2,%3}, {%4,%5,%6,%7}, {%8,%9}, {%0,%1,%2,%3};"
        : "+f"(c[0]), "+f"(c[1]), "+f"(c[2]), "+f"(c[3])
        : "r"(a[0]), "r"(a[1]), "r"(a[2]), "r"(a[3]), "r"(b[0]), "r"(b[1]));
}

// ---------------- small kernels -------------------------------------------------
__global__ void zero_stats_kernel() {
    int t = threadIdx.x;
    g_sum1[t] = 0.f; g_sq1[t] = 0.f;
    g_sum2[t] = 0.f; g_sq2[t] = 0.f;
}

// build weight smem-image: [chunk][hl][co][kk(36)]
__global__ void wsplit_img_kernel(const float* __restrict__ W, int Kdim, int total,
                                  __nv_bfloat16* __restrict__ out) {
    int idx = blockIdx.x * 256 + threadIdx.x;
    if (idx >= total) return;
    int kk = idx % ROWPAD;
    int co = (idx / ROWPAD) & 255;
    int hl = (idx / (ROWPAD * 256)) & 1;
    int chunk = idx / (ROWPAD * 256 * 2);
    float v = (kk < KC) ? W[(size_t)co * Kdim + chunk * KC + kk] : 0.f;
    __nv_bfloat16 h = __float2bfloat16(v);
    __nv_bfloat16 l = __float2bfloat16(v - __bfloat162float(h));
    out[idx] = hl ? l : h;
}

__global__ void __launch_bounds__(256) knn_kernel(
    const float* __restrict__ unknown, const float* __restrict__ known) {
    __shared__ float4 sk[M_];
    int b = blockIdx.y;
    const float* kb = known + (size_t)b * M_ * 3;
    for (int j = threadIdx.x; j < M_; j += blockDim.x)
        sk[j] = make_float4(kb[j * 3 + 0], kb[j * 3 + 1], kb[j * 3 + 2], 0.f);
    __syncthreads();

    int i = blockIdx.x * blockDim.x + threadIdx.x;
    const float* up = unknown + ((size_t)b * N_ + i) * 3;
    float px = up[0], py = up[1], pz = up[2];
    float bd0 = 1e30f, bd1 = 1e30f, bd2 = 1e30f;
    int   bi0 = 0, bi1 = 0, bi2 = 0;
    #pragma unroll 4
    for (int j = 0; j < M_; ++j) {
        float4 k4 = sk[j];
        float dx = px - k4.x, dy = py - k4.y, dz = pz - k4.z;
        float d = dx * dx + dy * dy + dz * dz;
        if (d < bd2) {
            if (d < bd1) {
                bd2 = bd1; bi2 = bi1;
                if (d < bd0) { bd1 = bd0; bi1 = bi0; bd0 = d; bi0 = j; }
                else         { bd1 = d;   bi1 = j; }
            } else { bd2 = d; bi2 = j; }
        }
    }
    float r0 = 1.f / (bd0 + 1e-8f), r1 = 1.f / (bd1 + 1e-8f), r2 = 1.f / (bd2 + 1e-8f);
    float rs = r0 + r1 + r2;
    size_t base = (size_t)b * 3 * N_ + i;
    g_idx[base + 0 * N_] = bi0; g_idx[base + 1 * N_] = bi1; g_idx[base + 2 * N_] = bi2;
    g_w[base + 0 * N_] = r0 / rs; g_w[base + 1 * N_] = r1 / rs; g_w[base + 2 * N_] = r2 / rs;
}

__global__ void __launch_bounds__(256) interp_kernel(const float* __restrict__ kf) {
    int b = blockIdx.y;
    int cg = blockIdx.x;
    const int*   ib = g_idx + (size_t)b * 3 * N_;
    const float* wb = g_w   + (size_t)b * 3 * N_;
    for (int i = threadIdx.x; i < N_; i += blockDim.x) {
        int i0 = ib[i], i1 = ib[i + N_], i2 = ib[i + 2 * N_];
        float w0 = wb[i], w1 = wb[i + N_], w2 = wb[i + 2 * N_];
        #pragma unroll
        for (int cc = 0; cc < 8; ++cc) {
            int c = cg * 8 + cc;
            const float* row = kf + ((size_t)b * C2_ + c) * M_;
            g_interp[((size_t)b * C2_ + c) * N_ + i] = w0 * row[i0] + w1 * row[i1] + w2 * row[i2];
        }
    }
}

// ---------------- split-bf16 HMMA GEMM -----------------------------------------
// D[co(256), n(128)] = W[co, K] * X[K, n], 3-pass split (ah*bh + al*bh + ah*bl).
// MODE 0: K=512, X = [g_interp | unknow_feats], out g_h1
// MODE 1: K=256, X = relu(bn1(g_h1)), out g_h2
template <int MODE>
__device__ __forceinline__ void loadB_regs(float4 xr[4], int b, int nb, int chunk,
                                           int tid, const float* __restrict__ uf) {
    int kp = tid >> 4;           // 0..15 -> k pair
    int n8 = (tid & 15) * 8;     // 0..120
    int k = chunk * KC + kp * 2;
    const float* r0;
    if constexpr (MODE == 0) {
        r0 = (k < C2_) ? g_interp + ((size_t)b * C2_ + k) * N_
                       : uf       + ((size_t)b * C1_ + (k - C2_)) * N_;
    } else {
        r0 = g_h1 + ((size_t)b * CO_ + k) * N_;
    }
    const float* p0 = r0 + nb + n8;
    xr[0] = *(const float4*)(p0);
    xr[1] = *(const float4*)(p0 + 4);
    xr[2] = *(const float4*)(p0 + N_);
    xr[3] = *(const float4*)(p0 + N_ + 4);
}

template <int MODE>
__device__ __forceinline__ void storeB(uint32_t* __restrict__ bhi, uint32_t* __restrict__ blo,
                                       float4 xr[4], int chunk, int tid) {
    int kp = tid >> 4;
    int n8 = (tid & 15) * 8;
    float x0[8] = {xr[0].x, xr[0].y, xr[0].z, xr[0].w, xr[1].x, xr[1].y, xr[1].z, xr[1].w};
    float x1[8] = {xr[2].x, xr[2].y, xr[2].z, xr[2].w, xr[3].x, xr[3].y, xr[3].z, xr[3].w};
    if constexpr (MODE == 1) {
        int kg = chunk * KC + kp * 2;
        float s0 = g_scale1[kg],     sh0 = g_shift1[kg];
        float s1 = g_scale1[kg + 1], sh1 = g_shift1[kg + 1];
        #pragma unroll
        for (int i = 0; i < 8; ++i) {
            x0[i] = fmaxf(fmaf(s0, x0[i], sh0), 0.f);
            x1[i] = fmaxf(fmaf(s1, x1[i], sh1), 0.f);
        }
    }
    #pragma unroll
    for (int i = 0; i < 8; ++i) {
        int n = n8 + i;
        __nv_bfloat16 h0 = __float2bfloat16(x0[i]);
        __nv_bfloat16 l0 = __float2bfloat16(x0[i] - __bfloat162float(h0));
        __nv_bfloat16 h1 = __float2bfloat16(x1[i]);
        __nv_bfloat16 l1 = __float2bfloat16(x1[i] - __bfloat162float(h1));
        uint32_t hw = (uint32_t)__bfloat16_as_ushort(h0) | ((uint32_t)__bfloat16_as_ushort(h1) << 16);
        uint32_t lw = (uint32_t)__bfloat16_as_ushort(l0) | ((uint32_t)__bfloat16_as_ushort(l1) << 16);
        bhi[n * 18 + kp] = hw;
        blo[n * 18 + kp] = lw;
    }
}

__device__ __forceinline__ void ldA(uint32_t a[4][4], const uint32_t* __restrict__ As,
                                    int wm, int g, int tig, int ks) {
    #pragma unroll
    for (int t = 0; t < 4; ++t) {
        int row = wm * 64 + t * 16 + g;
        int base = row * 18 + tig + ks * 8;
        a[t][0] = As[base];
        a[t][1] = As[base + 8 * 18];
        a[t][2] = As[base + 4];
        a[t][3] = As[base + 8 * 18 + 4];
    }
}
__device__ __forceinline__ void ldB(uint32_t bb[8][2], const uint32_t* __restrict__ Bs,
                                    int wn, int g, int tig, int ks) {
    #pragma unroll
    for (int u = 0; u < 8; ++u) {
        int row = wn * 64 + u * 8 + g;
        int base = row * 18 + tig + ks * 8;
        bb[u][0] = Bs[base];
        bb[u][1] = Bs[base + 4];
    }
}

template <int MODE>
__global__ void __launch_bounds__(256, 1) mma_gemm_kernel(const float* __restrict__ uf) {
    constexpr int Kdim = (MODE == 0) ? 512 : 256;
    constexpr int NC = Kdim / KC;

    extern __shared__ char dyn[];
    uint32_t sbase = smem_u32(dyn);

    int tid = threadIdx.x;
    int wid = tid >> 5, lane = tid & 31;
    int g = lane >> 2, tig = lane & 3;
    int wm = wid >> 1;          // 0..3 (M strips of 64)
    int wn = wid & 1;           // 0..1 (N strips of 64)
    int nb = blockIdx.x * TN;
    int b  = blockIdx.y;

    const __nv_bfloat16* img = (MODE == 0) ? g_w1img : g_w2img;

    float acc[4][8][4];
    #pragma unroll
    for (int t = 0; t < 4; ++t)
        #pragma unroll
        for (int u = 0; u < 8; ++u)
            #pragma unroll
            for (int v = 0; v < 4; ++v) acc[t][u][v] = 0.f;

    // prologue: chunk 0
    {
        const char* src = (const char*)img + tid * 16;
        uint32_t dst = sbase + tid * 16;
        #pragma unroll
        for (int j = 0; j < 9; ++j)
            CP_ASYNC16(dst + j * 4096, src + j * 4096);
        CP_COMMIT();
        float4 xr[4];
        loadB_regs<MODE>(xr, b, nb, 0, tid, uf);
        storeB<MODE>((uint32_t*)(dyn + B_BASE), (uint32_t*)(dyn + B_BASE + B_HL_BYTES), xr, 0, tid);
        CP_WAIT0();
        __syncthreads();
    }

    for (int c = 0; c < NC; ++c) {
        int p = c & 1, q = p ^ 1;
        float4 xr[4];
        if (c + 1 < NC) {
            const char* src = (const char*)img + (size_t)(c + 1) * A_STAGE_BYTES + tid * 16;
            uint32_t dst = sbase + q * A_STAGE_BYTES + tid * 16;
            #pragma unroll
            for (int j = 0; j < 9; ++j)
                CP_ASYNC16(dst + j * 4096, src + j * 4096);
            CP_COMMIT();
            loadB_regs<MODE>(xr, b, nb, c + 1, tid, uf);
        }

        const uint32_t* Ahi = (const uint32_t*)(dyn + p * A_STAGE_BYTES);
        const uint32_t* Alo = (const uint32_t*)(dyn + p * A_STAGE_BYTES + A_HL_BYTES);
        const uint32_t* Bhi = (const uint32_t*)(dyn + B_BASE + p * B_STAGE_BYTES);
        const uint32_t* Blo = (const uint32_t*)(dyn + B_BASE + p * B_STAGE_BYTES + B_HL_BYTES);

        uint32_t a[4][4], bb[8][2];
        #pragma unroll
        for (int ks = 0; ks < 2; ++ks) {
            // pass 1: ah * bh
            ldA(a, Ahi, wm, g, tig, ks);
            ldB(bb, Bhi, wn, g, tig, ks);
            #pragma unroll
            for (int t = 0; t < 4; ++t)
                #pragma unroll
                for (int u = 0; u < 8; ++u) mma16816(acc[t][u], a[t], bb[u]);
            // pass 2: ah * bl
            ldB(bb, Blo, wn, g, tig, ks);
            #pragma unroll
            for (int t = 0; t < 4; ++t)
                #pragma unroll
                for (int u = 0; u < 8; ++u) mma16816(acc[t][u], a[t], bb[u]);
            // pass 3: al * bh
            ldA(a, Alo, wm, g, tig, ks);
            ldB(bb, Bhi, wn, g, tig, ks);
            #pragma unroll
            for (int t = 0; t < 4; ++t)
                #pragma unroll
                for (int u = 0; u < 8; ++u) mma16816(acc[t][u], a[t], bb[u]);
        }

        if (c + 1 < NC) {
            storeB<MODE>((uint32_t*)(dyn + B_BASE + q * B_STAGE_BYTES),
                         (uint32_t*)(dyn + B_BASE + q * B_STAGE_BYTES + B_HL_BYTES), xr, c + 1, tid);
            CP_WAIT0();
        }
        __syncthreads();
    }

    // epilogue: store + fused BN stats
    float* out  = (MODE == 0) ? g_h1  : g_h2;
    float* gsum = (MODE == 0) ? g_sum1 : g_sum2;
    float* gsq  = (MODE == 0) ? g_sq1  : g_sq2;
    #pragma unroll
    for (int t = 0; t < 4; ++t) {
        int co0 = wm * 64 + t * 16 + g;
        int co1 = co0 + 8;
        float s0 = 0.f, q0 = 0.f, s1 = 0.f, q1 = 0.f;
        #pragma unroll
        for (int u = 0; u < 8; ++u) {
            int n = nb + wn * 64 + u * 8 + tig * 2;
            float2 v0 = make_float2(acc[t][u][0], acc[t][u][1]);
            float2 v1 = make_float2(acc[t][u][2], acc[t][u][3]);
            *(float2*)(out + ((size_t)b * CO_ + co0) * N_ + n) = v0;
            *(float2*)(out + ((size_t)b * CO_ + co1) * N_ + n) = v1;
            s0 += v0.x + v0.y; q0 += v0.x * v0.x + v0.y * v0.y;
            s1 += v1.x + v1.y; q1 += v1.x * v1.x + v1.y * v1.y;
        }
        #pragma unroll
        for (int o = 2; o > 0; o >>= 1) {
            s0 += __shfl_down_sync(0xffffffffu, s0, o);
            q0 += __shfl_down_sync(0xffffffffu, q0, o);
            s1 += __shfl_down_sync(0xffffffffu, s1, o);
            q1 += __shfl_down_sync(0xffffffffu, q1, o);
        }
        if (tig == 0) {
            atomicAdd(&gsum[co0], s0); atomicAdd(&gsq[co0], q0);
            atomicAdd(&gsum[co1], s1); atomicAdd(&gsq[co1], q1);
        }
    }
}

// ---------------- BN fold + final apply -----------------------------------------
template <int MODE>
__global__ void finalize_kernel(const float* __restrict__ g, const float* __restrict__ bb) {
    int c = threadIdx.x;
    float inv = 1.f / (float)(B_ * N_);
    float s  = (MODE == 0) ? g_sum1[c] : g_sum2[c];
    float sq = (MODE == 0) ? g_sq1[c]  : g_sq2[c];
    float mean = s * inv;
    float var  = sq * inv - mean * mean;
    float rstd = rsqrtf(var + 1e-5f);
    float sc = g[c] * rstd;
    float sh = bb[c] - mean * sc;
    if (MODE == 0) { g_scale1[c] = sc; g_shift1[c] = sh; }
    else           { g_scale2[c] = sc; g_shift2[c] = sh; }
}

__global__ void __launch_bounds__(256) apply_kernel(float* __restrict__ out) {
    size_t idx = (size_t)blockIdx.x * blockDim.x + threadIdx.x;
    int c = (int)((idx * 4 / N_) % CO_);
    float4 v = ((const float4*)g_h2)[idx];
    float sc = g_scale2[c], sh = g_shift2[c];
    v.x = fmaxf(fmaf(sc, v.x, sh), 0.f);
    v.y = fmaxf(fmaf(sc, v.y, sh), 0.f);
    v.z = fmaxf(fmaf(sc, v.z, sh), 0.f);
    v.w = fmaxf(fmaf(sc, v.w, sh), 0.f);
    ((float4*)out)[idx] = v;
}

// ---------------- launch ----------------------------------------------------------
extern "C" void kernel_launch(void* const* d_in, const int* in_sizes, int n_in,
                              void* d_out, int out_size) {
    const float* unknown      = (const float*)d_in[0];
    const float* known        = (const float*)d_in[1];
    const float* unknow_feats = (const float*)d_in[2];
    const float* known_feats  = (const float*)d_in[3];
    const float* W1 = (const float*)d_in[4];
    const float* g1 = (const float*)d_in[5];
    const float* b1 = (const float*)d_in[6];
    const float* W2 = (const float*)d_in[7];
    const float* g2 = (const float*)d_in[8];
    const float* b2 = (const float*)d_in[9];
    float* out = (float*)d_out;

    static bool attr_done = false;
    if (!attr_done) {
        cudaFuncSetAttribute(mma_gemm_kernel<0>, cudaFuncAttributeMaxDynamicSharedMemorySize, SMEM_TOTAL);
        cudaFuncSetAttribute(mma_gemm_kernel<1>, cudaFuncAttributeMaxDynamicSharedMemorySize, SMEM_TOTAL);
        attr_done = true;
    }

    zero_stats_kernel<<<1, 256>>>();
    __nv_bfloat16* w1img; cudaGetSymbolAddress((void**)&w1img, g_w1img);
    __nv_bfloat16* w2img; cudaGetSymbolAddress((void**)&w2img, g_w2img);
    {
        int tot1 = 16 * 2 * 256 * ROWPAD;
        wsplit_img_kernel<<<(tot1 + 255) / 256, 256>>>(W1, 512, tot1, w1img);
        int tot2 = 8 * 2 * 256 * ROWPAD;
        wsplit_img_kernel<<<(tot2 + 255) / 256, 256>>>(W2, 256, tot2, w2img);
    }
    knn_kernel<<<dim3(N_ / 256, B_), 256>>>(unknown, known);
    interp_kernel<<<dim3(C2_ / 8, B_), 256>>>(known_feats);

    dim3 ggrid(N_ / TN, B_);
    mma_gemm_kernel<0><<<ggrid, 256, SMEM_TOTAL>>>(unknow_feats);
    finalize_kernel<0><<<1, 256>>>(g1, b1);
    mma_gemm_kernel<1><<<ggrid, 256, SMEM_TOTAL>>>(nullptr);
    finalize_kernel<1><<<1, 256>>>(g2, b2);
    apply_kernel<<<(size_t)B_ * CO_ * (N_ / 4) / 256, 256>>>(out);
}